// round 15
// baseline (speedup 1.0000x reference)
#include <cuda_runtime.h>
#include <cuda_bf16.h>
#include <stdint.h>
#include <math.h>

#define D 256
#define NTHREADS 256
#define NWARPS (NTHREADS / 32)
#define DEPTH 5                    // rows in flight per warp
#define DYN_SMEM_BYTES (NWARPS * DEPTH * D * 4)   // 40 KB ring buffers

// ---- cp.async helpers ----
__device__ __forceinline__ void cp_async16(uint32_t dst_smem, const void* src) {
    asm volatile("cp.async.cg.shared.global [%0], [%1], 16;\n" :: "r"(dst_smem), "l"(src));
}
__device__ __forceinline__ void cp_commit() {
    asm volatile("cp.async.commit_group;\n");
}
template <int N>
__device__ __forceinline__ void cp_wait() {
    asm volatile("cp.async.wait_group %0;\n" :: "n"(N));
}

__device__ __forceinline__ float dot8(const float4& a0, const float4& a1,
                                      const float4& w0, const float4& w1) {
    float p;
    p = a0.x * w0.x;
    p = fmaf(a0.y, w0.y, p);
    p = fmaf(a0.z, w0.z, p);
    p = fmaf(a0.w, w0.w, p);
    p = fmaf(a1.x, w1.x, p);
    p = fmaf(a1.y, w1.y, p);
    p = fmaf(a1.z, w1.z, p);
    p = fmaf(a1.w, w1.w, p);
    return p;
}

// warp-collective lower_bound: first i in [0,n) with a[i] >= v (n if none).
// 32-ary search: ~3 rounds + final for n=500K.
__device__ __forceinline__ int warp_lower_bound(const int* __restrict__ a,
                                                int n, int v, int lane) {
    int lo = 0, hi = n;                 // answer in [lo, hi]
    while (hi - lo > 32) {
        const int chunk = (hi - lo + 31) >> 5;
        const int pos = lo + lane * chunk;
        const bool pred = (pos < hi) && (__ldg(a + pos) < v);
        const unsigned mask = __ballot_sync(0xffffffffu, pred);
        if (mask == 0) { hi = lo; break; }     // a[lo] >= v -> answer == lo
        const int L = 31 - __clz(mask);        // highest lane with a[pos] < v
        const int posL = lo + L * chunk;
        lo = posL + 1;
        hi = min(hi, posL + chunk + 1);
    }
    const int pos = lo + lane;
    const bool pred = (pos < hi) && (__ldg(a + pos) < v);
    return lo + __popc(__ballot_sync(0xffffffffu, pred));
}

__global__ void __launch_bounds__(NTHREADS, 5)
niche_attn_kernel(const float* __restrict__ x,
                  const float* __restrict__ w,
                  const float* __restrict__ bptr,
                  const int* __restrict__ batch,
                  float* __restrict__ out,
                  int N)
{
    __shared__ float wm[NWARPS], ws[NWARPS];
    __shared__ int bounds[2];
    extern __shared__ float ring[];        // [NWARPS][DEPTH][D]; reused
                                           // post-drain as per-warp comb rows

    const int seg  = blockIdx.x;
    const int tid  = threadIdx.x;
    const int lane = tid & 31;
    const int warp = tid >> 5;

    // ---- segment bounds: warps 0 and 1 search concurrently ----
    if (warp < 2) {
        const int r = warp_lower_bound(batch, N, seg + warp, lane);
        if (lane == 0) bounds[warp] = r;
    }

    const float4* w4 = reinterpret_cast<const float4*>(w);
    const float4 w0 = w4[lane];
    const float4 w1 = w4[32 + lane];
    const float bconst = bptr[0];

    __syncthreads();
    const int start = bounds[0];
    const int end   = bounds[1];

    // per-warp ring base; lane-exact mapping: lane L copies & reads
    // bytes [L*16, L*16+16) and [512+L*16, 512+L*16+16) of each row
    float* wring = ring + warp * (DEPTH * D);
    const uint32_t ring_u32 =
        (uint32_t)__cvta_generic_to_shared(wring) + (uint32_t)lane * 16u;
    const float* xbase = x;

    // ---- prologue: fill pipeline (one commit group per stage, always) ----
    #pragma unroll
    for (int s = 0; s < DEPTH; s++) {
        const int rr = start + warp + s * NWARPS;
        if (rr < end) {
            const char* src = reinterpret_cast<const char*>(xbase + (size_t)rr * D) + lane * 16;
            cp_async16(ring_u32 + s * 1024, src);
            cp_async16(ring_u32 + s * 1024 + 512, src + 512);
        }
        cp_commit();
    }

    float m_w = -INFINITY;
    float s_w = 0.0f;
    float4 acc0 = make_float4(0.f, 0.f, 0.f, 0.f);
    float4 acc1 = make_float4(0.f, 0.f, 0.f, 0.f);

    int st = 0;   // ring stage
    for (int r = start + warp; r < end; r += NWARPS) {
        cp_wait<DEPTH - 1>();     // oldest stage resident

        const float4* row4 = reinterpret_cast<const float4*>(wring + st * D);
        const float4 a0 = row4[lane];
        const float4 a1 = row4[32 + lane];

        // refill this stage with row r + DEPTH*NWARPS (commit unconditionally)
        const int rn = r + DEPTH * NWARPS;
        if (rn < end) {
            const char* src = reinterpret_cast<const char*>(xbase + (size_t)rn * D) + lane * 16;
            cp_async16(ring_u32 + st * 1024, src);
            cp_async16(ring_u32 + st * 1024 + 512, src + 512);
        }
        cp_commit();
        st = (st == DEPTH - 1) ? 0 : st + 1;

        // dot + butterfly -> warp-uniform score
        float d0 = dot8(a0, a1, w0, w1);
        #pragma unroll
        for (int o = 16; o; o >>= 1) d0 += __shfl_xor_sync(0xffffffffu, d0, o);
        const float s0 = d0 + bconst;

        if (s0 <= m_w) {
            const float e = __expf(s0 - m_w);
            s_w += e;
            acc0.x = fmaf(e, a0.x, acc0.x);
            acc0.y = fmaf(e, a0.y, acc0.y);
            acc0.z = fmaf(e, a0.z, acc0.z);
            acc0.w = fmaf(e, a0.w, acc0.w);
            acc1.x = fmaf(e, a1.x, acc1.x);
            acc1.y = fmaf(e, a1.y, acc1.y);
            acc1.z = fmaf(e, a1.z, acc1.z);
            acc1.w = fmaf(e, a1.w, acc1.w);
        } else {
            const float c = __expf(m_w - s0);   // 0 when m_w == -inf
            s_w = fmaf(s_w, c, 1.0f);
            acc0.x = fmaf(acc0.x, c, a0.x);
            acc0.y = fmaf(acc0.y, c, a0.y);
            acc0.z = fmaf(acc0.z, c, a0.z);
            acc0.w = fmaf(acc0.w, c, a0.w);
            acc1.x = fmaf(acc1.x, c, a1.x);
            acc1.y = fmaf(acc1.y, c, a1.y);
            acc1.z = fmaf(acc1.z, c, a1.z);
            acc1.w = fmaf(acc1.w, c, a1.w);
            m_w = s0;
        }
    }
    cp_wait<0>();   // this warp's ring region is now dead -> reuse as comb row

    // ---- stage warp partials into own (drained) ring slot ----
    float4* crow = reinterpret_cast<float4*>(wring);
    crow[lane]      = acc0;
    crow[32 + lane] = acc1;
    if (lane == 0) { wm[warp] = m_w; ws[warp] = s_w; }
    __syncthreads();   // all warps drained + staged before cross-warp reads

    // ---- combine: thread tid owns output column tid ----
    float M = -INFINITY;
    #pragma unroll
    for (int i = 0; i < NWARPS; i++) M = fmaxf(M, wm[i]);

    float val = 0.0f, s_tot = 0.0f;
    #pragma unroll
    for (int i = 0; i < NWARPS; i++) {
        const float mi = wm[i];
        const float sc = (mi == -INFINITY) ? 0.0f : __expf(mi - M);
        s_tot = fmaf(ws[i], sc, s_tot);
        val   = fmaf(ring[i * (DEPTH * D) + tid], sc, val);
    }

    out[(size_t)seg * D + tid] = (s_tot > 0.0f) ? (val / s_tot) : 0.0f;
}

extern "C" void kernel_launch(void* const* d_in, const int* in_sizes, int n_in,
                              void* d_out, int out_size)
{
    const float* x     = (const float*)d_in[0];
    const float* w     = (const float*)d_in[1];
    const float* bptr  = (const float*)d_in[2];
    const int*   batch = (const int*)d_in[3];

    const int N = in_sizes[3];
    const int B = out_size / D;

    cudaFuncSetAttribute(niche_attn_kernel,
                         cudaFuncAttributeMaxDynamicSharedMemorySize, DYN_SMEM_BYTES);
    niche_attn_kernel<<<B, NTHREADS, DYN_SMEM_BYTES>>>(
        x, w, bptr, batch, (float*)d_out, N);
}

// round 16
// speedup vs baseline: 1.1367x; 1.1367x over previous
#include <cuda_runtime.h>
#include <cuda_bf16.h>
#include <stdint.h>
#include <math.h>

#define D 256
#define NTHREADS 256
#define NWARPS (NTHREADS / 32)
#define DEPTH 6                    // rows in flight per warp
#define MAXB 4100

#define DYN_SMEM_BYTES (NWARPS * DEPTH * D * 4)   // 48 KB ring buffers

__device__ int g_seg_start[MAXB];

// ---- kernel 1: segment boundaries from sorted batch (parallel diff-scatter) ----
__global__ void bounds_kernel(const int* __restrict__ batch, int N, int B) {
    int i = blockIdx.x * blockDim.x + threadIdx.x;
    if (i > N) return;
    int cur  = (i < N) ? batch[i]     : B;
    int prev = (i > 0) ? batch[i - 1] : -1;
    for (int b = prev + 1; b <= cur && b <= B; b++) g_seg_start[b] = i;
}

// ---- cp.async helpers ----
__device__ __forceinline__ void cp_async16(uint32_t dst_smem, const void* src) {
    asm volatile("cp.async.cg.shared.global [%0], [%1], 16;\n" :: "r"(dst_smem), "l"(src));
}
__device__ __forceinline__ void cp_commit() {
    asm volatile("cp.async.commit_group;\n");
}
template <int N>
__device__ __forceinline__ void cp_wait() {
    asm volatile("cp.async.wait_group %0;\n" :: "n"(N));
}

__device__ __forceinline__ float dot8(const float4& a0, const float4& a1,
                                      const float4& w0, const float4& w1) {
    float p;
    p = a0.x * w0.x;
    p = fmaf(a0.y, w0.y, p);
    p = fmaf(a0.z, w0.z, p);
    p = fmaf(a0.w, w0.w, p);
    p = fmaf(a1.x, w1.x, p);
    p = fmaf(a1.y, w1.y, p);
    p = fmaf(a1.z, w1.z, p);
    p = fmaf(a1.w, w1.w, p);
    return p;
}

__global__ void __launch_bounds__(NTHREADS, 4)
niche_attn_kernel(const float* __restrict__ x,
                  const float* __restrict__ w,
                  const float* __restrict__ bptr,
                  float* __restrict__ out)
{
    __shared__ float comb[NWARPS * D];
    __shared__ float wm[NWARPS], ws[NWARPS];
    extern __shared__ float ring[];        // [NWARPS][DEPTH][D]

    const int seg  = blockIdx.x;
    const int tid  = threadIdx.x;
    const int lane = tid & 31;
    const int warp = tid >> 5;

    const int start = g_seg_start[seg];
    const int end   = g_seg_start[seg + 1];

    const float4* w4 = reinterpret_cast<const float4*>(w);
    const float4 w0 = w4[lane];
    const float4 w1 = w4[32 + lane];
    const float bconst = bptr[0];

    // per-warp ring base; lane-exact mapping: lane L copies & reads
    // bytes [L*16, L*16+16) and [512+L*16, 512+L*16+16) of each row
    float* wring = ring + warp * (DEPTH * D);
    const uint32_t ring_u32 =
        (uint32_t)__cvta_generic_to_shared(wring) + (uint32_t)lane * 16u;
    const float* xbase = x;

    // ---- prologue: fill pipeline (one commit group per stage, always) ----
    #pragma unroll
    for (int s = 0; s < DEPTH; s++) {
        const int rr = start + warp + s * NWARPS;
        if (rr < end) {
            const char* src = reinterpret_cast<const char*>(xbase + (size_t)rr * D) + lane * 16;
            cp_async16(ring_u32 + s * 1024, src);
            cp_async16(ring_u32 + s * 1024 + 512, src + 512);
        }
        cp_commit();
    }

    float m_w = -INFINITY;
    float s_w = 0.0f;
    float4 acc0 = make_float4(0.f, 0.f, 0.f, 0.f);
    float4 acc1 = make_float4(0.f, 0.f, 0.f, 0.f);

    int st = 0;   // ring stage
    for (int r = start + warp; r < end; r += NWARPS) {
        cp_wait<DEPTH - 1>();     // oldest stage resident

        const float4* row4 = reinterpret_cast<const float4*>(wring + st * D);
        const float4 a0 = row4[lane];
        const float4 a1 = row4[32 + lane];

        // refill this stage with row r + DEPTH*NWARPS (commit unconditionally)
        const int rn = r + DEPTH * NWARPS;
        if (rn < end) {
            const char* src = reinterpret_cast<const char*>(xbase + (size_t)rn * D) + lane * 16;
            cp_async16(ring_u32 + st * 1024, src);
            cp_async16(ring_u32 + st * 1024 + 512, src + 512);
        }
        cp_commit();
        st = (st == DEPTH - 1) ? 0 : st + 1;

        // dot + butterfly -> warp-uniform score
        float d0 = dot8(a0, a1, w0, w1);
        #pragma unroll
        for (int o = 16; o; o >>= 1) d0 += __shfl_xor_sync(0xffffffffu, d0, o);
        const float s0 = d0 + bconst;

        if (s0 <= m_w) {
            const float e = __expf(s0 - m_w);
            s_w += e;
            acc0.x = fmaf(e, a0.x, acc0.x);
            acc0.y = fmaf(e, a0.y, acc0.y);
            acc0.z = fmaf(e, a0.z, acc0.z);
            acc0.w = fmaf(e, a0.w, acc0.w);
            acc1.x = fmaf(e, a1.x, acc1.x);
            acc1.y = fmaf(e, a1.y, acc1.y);
            acc1.z = fmaf(e, a1.z, acc1.z);
            acc1.w = fmaf(e, a1.w, acc1.w);
        } else {
            const float c = __expf(m_w - s0);   // 0 when m_w == -inf
            s_w = fmaf(s_w, c, 1.0f);
            acc0.x = fmaf(acc0.x, c, a0.x);
            acc0.y = fmaf(acc0.y, c, a0.y);
            acc0.z = fmaf(acc0.z, c, a0.z);
            acc0.w = fmaf(acc0.w, c, a0.w);
            acc1.x = fmaf(acc1.x, c, a1.x);
            acc1.y = fmaf(acc1.y, c, a1.y);
            acc1.z = fmaf(acc1.z, c, a1.z);
            acc1.w = fmaf(acc1.w, c, a1.w);
            m_w = s0;
        }
    }
    cp_wait<0>();   // drain before smem reuse / exit

    // ---- stage warp partials ----
    float4* crow = reinterpret_cast<float4*>(comb + warp * D);
    crow[lane]      = acc0;
    crow[32 + lane] = acc1;
    if (lane == 0) { wm[warp] = m_w; ws[warp] = s_w; }
    __syncthreads();

    // ---- combine: thread tid owns output column tid ----
    float M = -INFINITY;
    #pragma unroll
    for (int i = 0; i < NWARPS; i++) M = fmaxf(M, wm[i]);

    float val = 0.0f, s_tot = 0.0f;
    #pragma unroll
    for (int i = 0; i < NWARPS; i++) {
        const float mi = wm[i];
        const float sc = (mi == -INFINITY) ? 0.0f : __expf(mi - M);
        s_tot = fmaf(ws[i], sc, s_tot);
        val   = fmaf(comb[i * D + tid], sc, val);
    }

    out[(size_t)seg * D + tid] = (s_tot > 0.0f) ? (val / s_tot) : 0.0f;
}

extern "C" void kernel_launch(void* const* d_in, const int* in_sizes, int n_in,
                              void* d_out, int out_size)
{
    const float* x     = (const float*)d_in[0];
    const float* w     = (const float*)d_in[1];
    const float* bptr  = (const float*)d_in[2];
    const int*   batch = (const int*)d_in[3];

    const int N = in_sizes[3];
    const int B = out_size / D;

    bounds_kernel<<<(N + 1 + 255) / 256, 256>>>(batch, N, B);

    cudaFuncSetAttribute(niche_attn_kernel,
                         cudaFuncAttributeMaxDynamicSharedMemorySize, DYN_SMEM_BYTES);
    niche_attn_kernel<<<B, NTHREADS, DYN_SMEM_BYTES>>>(x, w, bptr, (float*)d_out);
}

// round 17
// speedup vs baseline: 1.1441x; 1.0065x over previous
#include <cuda_runtime.h>
#include <cuda_bf16.h>
#include <stdint.h>
#include <math.h>

#define D 256
#define NTHREADS 256
#define NWARPS (NTHREADS / 32)
#define DEPTH 6                    // rows in flight per warp
#define MAXB 4100

#define DYN_SMEM_BYTES (NWARPS * DEPTH * D * 4)   // 48 KB ring buffers

__device__ int g_seg_start[MAXB];

// ---- kernel 1: segment boundaries from sorted batch (parallel diff-scatter) ----
__global__ void bounds_kernel(const int* __restrict__ batch, int N, int B) {
    int i = blockIdx.x * blockDim.x + threadIdx.x;
    if (i <= N) {
        int cur  = (i < N) ? batch[i]     : B;
        int prev = (i > 0) ? batch[i - 1] : -1;
        for (int b = prev + 1; b <= cur && b <= B; b++) g_seg_start[b] = i;
    }
    // signal dependent (main) kernel it may start its bounds-dependent phase
    cudaTriggerProgrammaticLaunchCompletion();
}

// ---- cp.async helpers ----
__device__ __forceinline__ void cp_async16(uint32_t dst_smem, const void* src) {
    asm volatile("cp.async.cg.shared.global [%0], [%1], 16;\n" :: "r"(dst_smem), "l"(src));
}
__device__ __forceinline__ void cp_commit() {
    asm volatile("cp.async.commit_group;\n");
}
template <int N>
__device__ __forceinline__ void cp_wait() {
    asm volatile("cp.async.wait_group %0;\n" :: "n"(N));
}

__device__ __forceinline__ float dot8(const float4& a0, const float4& a1,
                                      const float4& w0, const float4& w1) {
    float p;
    p = a0.x * w0.x;
    p = fmaf(a0.y, w0.y, p);
    p = fmaf(a0.z, w0.z, p);
    p = fmaf(a0.w, w0.w, p);
    p = fmaf(a1.x, w1.x, p);
    p = fmaf(a1.y, w1.y, p);
    p = fmaf(a1.z, w1.z, p);
    p = fmaf(a1.w, w1.w, p);
    return p;
}

__global__ void __launch_bounds__(NTHREADS, 4)
niche_attn_kernel(const float* __restrict__ x,
                  const float* __restrict__ w,
                  const float* __restrict__ bptr,
                  float* __restrict__ out)
{
    __shared__ float comb[NWARPS * D];
    __shared__ float wm[NWARPS], ws[NWARPS];
    extern __shared__ float ring[];        // [NWARPS][DEPTH][D]

    const int seg  = blockIdx.x;
    const int tid  = threadIdx.x;
    const int lane = tid & 31;
    const int warp = tid >> 5;

    // ---- bounds-independent setup (overlaps bounds_kernel via PDL) ----
    const float4* w4 = reinterpret_cast<const float4*>(w);
    const float4 w0 = w4[lane];
    const float4 w1 = w4[32 + lane];
    const float bconst = bptr[0];

    float* wring = ring + warp * (DEPTH * D);
    const uint32_t ring_u32 =
        (uint32_t)__cvta_generic_to_shared(wring) + (uint32_t)lane * 16u;
    const float* xbase = x;

    // ---- wait for bounds_kernel's writes to be visible ----
    cudaGridDependencySynchronize();

    const int start = g_seg_start[seg];
    const int end   = g_seg_start[seg + 1];

    // per-warp ring; lane-exact mapping: lane L copies & reads
    // bytes [L*16, L*16+16) and [512+L*16, 512+L*16+16) of each row

    // ---- prologue: fill pipeline (one commit group per stage, always) ----
    #pragma unroll
    for (int s = 0; s < DEPTH; s++) {
        const int rr = start + warp + s * NWARPS;
        if (rr < end) {
            const char* src = reinterpret_cast<const char*>(xbase + (size_t)rr * D) + lane * 16;
            cp_async16(ring_u32 + s * 1024, src);
            cp_async16(ring_u32 + s * 1024 + 512, src + 512);
        }
        cp_commit();
    }

    float m_w = -INFINITY;
    float s_w = 0.0f;
    float4 acc0 = make_float4(0.f, 0.f, 0.f, 0.f);
    float4 acc1 = make_float4(0.f, 0.f, 0.f, 0.f);

    int st = 0;   // ring stage
    for (int r = start + warp; r < end; r += NWARPS) {
        cp_wait<DEPTH - 1>();     // oldest stage resident

        const float4* row4 = reinterpret_cast<const float4*>(wring + st * D);
        const float4 a0 = row4[lane];
        const float4 a1 = row4[32 + lane];

        // refill this stage with row r + DEPTH*NWARPS (commit unconditionally)
        const int rn = r + DEPTH * NWARPS;
        if (rn < end) {
            const char* src = reinterpret_cast<const char*>(xbase + (size_t)rn * D) + lane * 16;
            cp_async16(ring_u32 + st * 1024, src);
            cp_async16(ring_u32 + st * 1024 + 512, src + 512);
        }
        cp_commit();
        st = (st == DEPTH - 1) ? 0 : st + 1;

        // dot + butterfly -> warp-uniform score
        float d0 = dot8(a0, a1, w0, w1);
        #pragma unroll
        for (int o = 16; o; o >>= 1) d0 += __shfl_xor_sync(0xffffffffu, d0, o);
        const float s0 = d0 + bconst;

        if (s0 <= m_w) {
            const float e = __expf(s0 - m_w);
            s_w += e;
            acc0.x = fmaf(e, a0.x, acc0.x);
            acc0.y = fmaf(e, a0.y, acc0.y);
            acc0.z = fmaf(e, a0.z, acc0.z);
            acc0.w = fmaf(e, a0.w, acc0.w);
            acc1.x = fmaf(e, a1.x, acc1.x);
            acc1.y = fmaf(e, a1.y, acc1.y);
            acc1.z = fmaf(e, a1.z, acc1.z);
            acc1.w = fmaf(e, a1.w, acc1.w);
        } else {
            const float c = __expf(m_w - s0);   // 0 when m_w == -inf
            s_w = fmaf(s_w, c, 1.0f);
            acc0.x = fmaf(acc0.x, c, a0.x);
            acc0.y = fmaf(acc0.y, c, a0.y);
            acc0.z = fmaf(acc0.z, c, a0.z);
            acc0.w = fmaf(acc0.w, c, a0.w);
            acc1.x = fmaf(acc1.x, c, a1.x);
            acc1.y = fmaf(acc1.y, c, a1.y);
            acc1.z = fmaf(acc1.z, c, a1.z);
            acc1.w = fmaf(acc1.w, c, a1.w);
            m_w = s0;
        }
    }
    cp_wait<0>();   // drain before smem reuse / exit

    // ---- stage warp partials ----
    float4* crow = reinterpret_cast<float4*>(comb + warp * D);
    crow[lane]      = acc0;
    crow[32 + lane] = acc1;
    if (lane == 0) { wm[warp] = m_w; ws[warp] = s_w; }
    __syncthreads();

    // ---- combine: thread tid owns output column tid ----
    float M = -INFINITY;
    #pragma unroll
    for (int i = 0; i < NWARPS; i++) M = fmaxf(M, wm[i]);

    float val = 0.0f, s_tot = 0.0f;
    #pragma unroll
    for (int i = 0; i < NWARPS; i++) {
        const float mi = wm[i];
        const float sc = (mi == -INFINITY) ? 0.0f : __expf(mi - M);
        s_tot = fmaf(ws[i], sc, s_tot);
        val   = fmaf(comb[i * D + tid], sc, val);
    }

    out[(size_t)seg * D + tid] = (s_tot > 0.0f) ? (val / s_tot) : 0.0f;
}

extern "C" void kernel_launch(void* const* d_in, const int* in_sizes, int n_in,
                              void* d_out, int out_size)
{
    const float* x     = (const float*)d_in[0];
    const float* w     = (const float*)d_in[1];
    const float* bptr  = (const float*)d_in[2];
    const int*   batch = (const int*)d_in[3];

    const int N = in_sizes[3];
    const int B = out_size / D;

    bounds_kernel<<<(N + 1 + 255) / 256, 256>>>(batch, N, B);

    cudaFuncSetAttribute(niche_attn_kernel,
                         cudaFuncAttributeMaxDynamicSharedMemorySize, DYN_SMEM_BYTES);

    // PDL: main kernel launches while bounds_kernel runs; CTAs do
    // bounds-independent setup, then cudaGridDependencySynchronize().
    cudaLaunchConfig_t cfg = {};
    cfg.gridDim = dim3(B, 1, 1);
    cfg.blockDim = dim3(NTHREADS, 1, 1);
    cfg.dynamicSmemBytes = DYN_SMEM_BYTES;
    cfg.stream = 0;
    cudaLaunchAttribute attrs[1];
    attrs[0].id = cudaLaunchAttributeProgrammaticStreamSerialization;
    attrs[0].val.programmaticStreamSerializationAllowed = 1;
    cfg.attrs = attrs;
    cfg.numAttrs = 1;
    cudaLaunchKernelEx(&cfg, niche_attn_kernel, x, w, bptr, (float*)d_out);
}